// round 1
// baseline (speedup 1.0000x reference)
#include <cuda_runtime.h>
#include <cstdint>
#include <math.h>

// ---------------------------------------------------------------------------
// Problem constants (shapes fixed by the dataset)
// ---------------------------------------------------------------------------
#define HID 128
#define NHEAD 8
#define HDIM 16

#define NH_MAX 8000
#define NI_MAX 40000
#define NT_MAX 20000
#define NN_MAX (NH_MAX + NI_MAX + NT_MAX)           // 68000
#define NREL_MAX (NH_MAX + 2*NI_MAX + NT_MAX)       // 108000
#define MAXE 250000

// ---------------------------------------------------------------------------
// Device scratch (static globals; no allocation anywhere)
// ---------------------------------------------------------------------------
__device__ float g_xs   [(size_t)NN_MAX   * HID];
__device__ float g_q    [(size_t)NN_MAX   * HID];   // reused as gelu buffer later
__device__ float g_krel [(size_t)NREL_MAX * HID];
__device__ float g_vrel [(size_t)NREL_MAX * HID];
__device__ float g_logits[(size_t)4 * MAXE * NHEAD];
__device__ float g_mx   [(size_t)NN_MAX * NHEAD];
__device__ float g_den  [(size_t)NN_MAX * NHEAD];
__device__ float g_agg  [(size_t)NN_MAX * HID];
__device__ float g_htmp [(size_t)NH_MAX * HID];
__device__ float g_wf   [8 * HID * HID];            // fused rel weights [e*2+kind][128][128]
__device__ float g_bf   [8 * HID];                  // fused rel biases

// ---------------------------------------------------------------------------
// init: agg=0, den=0, mx=-inf
// ---------------------------------------------------------------------------
__global__ void init_buffers(float* __restrict__ agg, float* __restrict__ den,
                             float* __restrict__ mx, int nAgg, int nDH)
{
    int idx = blockIdx.x * blockDim.x + threadIdx.x;
    int total = nAgg + 2 * nDH;
    if (idx >= total) return;
    if (idx < nAgg)            agg[idx] = 0.0f;
    else if (idx < nAgg + nDH) den[idx - nAgg] = 0.0f;
    else                       mx[idx - nAgg - nDH] = -INFINITY;
}

// ---------------------------------------------------------------------------
// Fuse Wk/Wv with per-edge-type relation matrices:
//   Wf[e,kind][i][j] = sum_d W[srctype][i][h*16+d] * rel[e][h][d][j%16],  h=j/16
//   bf likewise from the bias.
// blockIdx.x = slot = e*2 + kind (kind 0 = k/a_rel, 1 = v/m_rel)
// ---------------------------------------------------------------------------
__global__ void fuse_rel_weights(const float* __restrict__ Wk, const float* __restrict__ bk,
                                 const float* __restrict__ Wv, const float* __restrict__ bv,
                                 const float* __restrict__ a_rel, const float* __restrict__ m_rel,
                                 float* __restrict__ Wf, float* __restrict__ bf)
{
    int slot = blockIdx.x;
    int e = slot >> 1, kind = slot & 1;
    int s = (e == 0) ? 0 : ((e == 3) ? 2 : 1);      // src node type of edge type e
    const float* Wb = (kind ? Wv : Wk) + (size_t)s * HID * HID;
    const float* bb = (kind ? bv : bk) + (size_t)s * HID;
    const float* rel = (kind ? m_rel : a_rel) + (size_t)e * NHEAD * HDIM * HDIM;

    for (int idx = threadIdx.x; idx < HID * HID; idx += blockDim.x) {
        int i = idx >> 7, j = idx & 127;
        int h = j >> 4, j16 = j & 15;
        float acc = 0.0f;
        #pragma unroll
        for (int d = 0; d < HDIM; ++d)
            acc += Wb[i * HID + h * HDIM + d] * rel[(h * HDIM + d) * HDIM + j16];
        Wf[(size_t)slot * HID * HID + idx] = acc;
    }
    for (int j = threadIdx.x; j < HID; j += blockDim.x) {
        int h = j >> 4, j16 = j & 15;
        float acc = 0.0f;
        #pragma unroll
        for (int d = 0; d < HDIM; ++d)
            acc += bb[h * HDIM + d] * rel[(h * HDIM + d) * HDIM + j16];
        bf[slot * HID + j] = acc;
    }
}

// ---------------------------------------------------------------------------
// SGEMM: C[M,128] = A[M,K] @ W[K,128] + bias
// mode 0: plain.  mode 1: relu(g*C + (1-g)*xs), g = sigmoid(skipv[skipidx]).
// tile 64x128, 256 threads, per-thread 8x4 register block.
// Requires K % 4 == 0 (true: 400/300/200/128).
// ---------------------------------------------------------------------------
#define TM 64
#define TK 32

__global__ __launch_bounds__(256)
void sgemm128(const float* __restrict__ A, const float* __restrict__ W,
              const float* __restrict__ bias, float* __restrict__ C,
              int M, int K, int mode,
              const float* __restrict__ xs,
              const float* __restrict__ skipv, int skipidx)
{
    __shared__ float As[TM * TK];     // [row][k], row stride TK
    __shared__ float Bs[TK * HID];    // [k][col]

    const int tx = threadIdx.x;
    const int m0 = blockIdx.x * TM;
    const int colg = tx & 31;          // col group
    const int rowg = tx >> 5;          // 0..7
    const int r0 = rowg * 8;
    const int c0 = colg * 4;

    float acc[8][4];
    #pragma unroll
    for (int i = 0; i < 8; ++i)
        #pragma unroll
        for (int j = 0; j < 4; ++j) acc[i][j] = 0.0f;

    const int la_r = tx >> 2;          // 0..63
    const int la_k = (tx & 3) * 8;     // 0,8,16,24
    const int lb_r = tx >> 3;          // 0..31
    const int lb_c = (tx & 7) * 16;    // 0..112

    const int ktiles = (K + TK - 1) / TK;
    for (int kt = 0; kt < ktiles; ++kt) {
        const int k0 = kt * TK;
        // load A tile (zero-padded)
        #pragma unroll
        for (int j = 0; j < 2; ++j) {
            int kk = la_k + j * 4;
            int gr = m0 + la_r, gk = k0 + kk;
            float4 v = make_float4(0.f, 0.f, 0.f, 0.f);
            if (gr < M && gk < K)
                v = *reinterpret_cast<const float4*>(A + (size_t)gr * K + gk);
            *reinterpret_cast<float4*>(As + la_r * TK + kk) = v;
        }
        // load B tile
        #pragma unroll
        for (int j = 0; j < 4; ++j) {
            int cc = lb_c + j * 4;
            int gk = k0 + lb_r;
            float4 v = make_float4(0.f, 0.f, 0.f, 0.f);
            if (gk < K)
                v = *reinterpret_cast<const float4*>(W + (size_t)gk * HID + cc);
            *reinterpret_cast<float4*>(Bs + lb_r * HID + cc) = v;
        }
        __syncthreads();
        #pragma unroll
        for (int kk = 0; kk < TK; ++kk) {
            float4 b = *reinterpret_cast<const float4*>(Bs + kk * HID + c0);
            #pragma unroll
            for (int i = 0; i < 8; ++i) {
                float a = As[(r0 + i) * TK + kk];
                acc[i][0] = fmaf(a, b.x, acc[i][0]);
                acc[i][1] = fmaf(a, b.y, acc[i][1]);
                acc[i][2] = fmaf(a, b.z, acc[i][2]);
                acc[i][3] = fmaf(a, b.w, acc[i][3]);
            }
        }
        __syncthreads();
    }

    float4 bv = *reinterpret_cast<const float4*>(bias + c0);
    float g = 0.0f;
    if (mode == 1) g = 1.0f / (1.0f + expf(-skipv[skipidx]));

    #pragma unroll
    for (int i = 0; i < 8; ++i) {
        int gr = m0 + r0 + i;
        if (gr < M) {
            float4 o;
            o.x = acc[i][0] + bv.x;
            o.y = acc[i][1] + bv.y;
            o.z = acc[i][2] + bv.z;
            o.w = acc[i][3] + bv.w;
            if (mode == 1) {
                float4 xv = *reinterpret_cast<const float4*>(xs + (size_t)gr * HID + c0);
                float h = 1.0f - g;
                o.x = fmaxf(0.f, g * o.x + h * xv.x);
                o.y = fmaxf(0.f, g * o.y + h * xv.y);
                o.z = fmaxf(0.f, g * o.z + h * xv.z);
                o.w = fmaxf(0.f, g * o.w + h * xv.w);
            }
            *reinterpret_cast<float4*>(C + (size_t)gr * HID + c0) = o;
        }
    }
}

// ---------------------------------------------------------------------------
// Edge pass A: logit[e,h] = (q[dst] . k_rel[src])_h * p_rel[h]/4; segment max.
// 1 warp / edge; lanes l cover head l>>2, dims (l&3)*4..+3.
// ---------------------------------------------------------------------------
__global__ __launch_bounds__(256)
void edge_pass_a(const int* __restrict__ src, const int* __restrict__ dst, int E,
                 const float* __restrict__ q, const float* __restrict__ krel,
                 float* __restrict__ logits, float* __restrict__ mx,
                 const float* __restrict__ prel)
{
    const int lane = threadIdx.x & 31;
    const int head = lane >> 2;
    const float scale = __ldg(prel + head) * 0.25f;   // p_rel[h] / sqrt(16)
    int warp = (blockIdx.x * blockDim.x + threadIdx.x) >> 5;
    const int nwarp = (gridDim.x * blockDim.x) >> 5;

    for (int e = warp; e < E; e += nwarp) {
        int s = __ldg(src + e);
        int d = __ldg(dst + e);
        float4 qv = *reinterpret_cast<const float4*>(q    + (size_t)d * HID + lane * 4);
        float4 kv = *reinterpret_cast<const float4*>(krel + (size_t)s * HID + lane * 4);
        float p = qv.x * kv.x + qv.y * kv.y + qv.z * kv.z + qv.w * kv.w;
        p += __shfl_xor_sync(0xffffffffu, p, 1);
        p += __shfl_xor_sync(0xffffffffu, p, 2);
        float lg = p * scale;
        if ((lane & 3) == 0) {
            logits[(size_t)e * NHEAD + head] = lg;
            float* a = mx + (size_t)d * NHEAD + head;
            // lattice-monotone float max via sign-split int/uint atomics
            if (lg >= 0.0f) atomicMax((int*)a, __float_as_int(lg));
            else            atomicMin((unsigned int*)a, __float_as_uint(lg));
        }
    }
}

// ---------------------------------------------------------------------------
// Edge pass B: ex = exp(logit - mx[dst]); den += ex; agg[dst] += ex * v_rel[src]
// using vector reductions (red.global.add.v4.f32).
// ---------------------------------------------------------------------------
__global__ __launch_bounds__(256)
void edge_pass_b(const int* __restrict__ src, const int* __restrict__ dst, int E,
                 const float* __restrict__ logits, const float* __restrict__ mx,
                 const float* __restrict__ vrel,
                 float* __restrict__ den, float* __restrict__ agg)
{
    const int lane = threadIdx.x & 31;
    const int head = lane >> 2;
    int warp = (blockIdx.x * blockDim.x + threadIdx.x) >> 5;
    const int nwarp = (gridDim.x * blockDim.x) >> 5;

    for (int e = warp; e < E; e += nwarp) {
        int s = __ldg(src + e);
        int d = __ldg(dst + e);
        float lg = __ldg(logits + (size_t)e * NHEAD + head);
        float m  = __ldg(mx + (size_t)d * NHEAD + head);
        float ex = __expf(lg - m);
        if ((lane & 3) == 0)
            atomicAdd(den + (size_t)d * NHEAD + head, ex);
        float4 vv = *reinterpret_cast<const float4*>(vrel + (size_t)s * HID + lane * 4);
        float* a = agg + (size_t)d * HID + lane * 4;
        asm volatile("red.global.add.v4.f32 [%0], {%1,%2,%3,%4};"
                     :: "l"(a), "f"(ex * vv.x), "f"(ex * vv.y),
                        "f"(ex * vv.z), "f"(ex * vv.w)
                     : "memory");
    }
}

// ---------------------------------------------------------------------------
// normalize + exact GELU:  out = gelu(agg / (den + 1e-16))
// ---------------------------------------------------------------------------
__global__ void norm_gelu(const float* __restrict__ agg, const float* __restrict__ den,
                          float* __restrict__ out, int total)
{
    int idx = blockIdx.x * blockDim.x + threadIdx.x;
    if (idx >= total) return;
    int n = idx >> 7;
    int h = (idx >> 4) & 7;
    float x = agg[idx] / (den[n * NHEAD + h] + 1e-16f);
    out[idx] = 0.5f * x * (1.0f + erff(x * 0.70710678118654752f));
}

// ---------------------------------------------------------------------------
// kernel_launch
// ---------------------------------------------------------------------------
static inline int cdiv(int a, int b) { return (a + b - 1) / b; }

extern "C" void kernel_launch(void* const* d_in, const int* in_sizes, int n_in,
                              void* d_out, int out_size)
{
    const float* x_herb = (const float*)d_in[0];
    const float* x_ing  = (const float*)d_in[1];
    const float* x_tgt  = (const float*)d_in[2];
    const float* W_herb = (const float*)d_in[3];
    const float* b_herb = (const float*)d_in[4];
    const float* W_ing  = (const float*)d_in[5];
    const float* b_ing  = (const float*)d_in[6];
    const float* W_tgt  = (const float*)d_in[7];
    const float* b_tgt  = (const float*)d_in[8];
    const float* Wk     = (const float*)d_in[9];
    const float* bk     = (const float*)d_in[10];
    const float* Wq     = (const float*)d_in[11];
    const float* bq     = (const float*)d_in[12];
    const float* Wv     = (const float*)d_in[13];
    const float* bv     = (const float*)d_in[14];
    const float* a_rel  = (const float*)d_in[15];
    const float* m_rel  = (const float*)d_in[16];
    const float* p_rel  = (const float*)d_in[17];
    const float* Wa     = (const float*)d_in[18];
    const float* ba     = (const float*)d_in[19];
    const float* skip   = (const float*)d_in[20];
    const float* W_out  = (const float*)d_in[21];
    const float* b_out  = (const float*)d_in[22];
    const int* src_e[4] = { (const int*)d_in[23], (const int*)d_in[25],
                            (const int*)d_in[27], (const int*)d_in[29] };
    const int* dst_e[4] = { (const int*)d_in[24], (const int*)d_in[26],
                            (const int*)d_in[28], (const int*)d_in[30] };

    const int Nh = in_sizes[0] / 400;
    const int Ni = in_sizes[1] / 300;
    const int Nt = in_sizes[2] / 200;
    const int NN = Nh + Ni + Nt;
    int E[4] = { in_sizes[23], in_sizes[25], in_sizes[27], in_sizes[29] };

    // scratch pointers
    float *xs, *q, *krel, *vrel, *logits, *mx, *den, *agg, *htmp, *wf, *bf;
    cudaGetSymbolAddress((void**)&xs, g_xs);
    cudaGetSymbolAddress((void**)&q, g_q);
    cudaGetSymbolAddress((void**)&krel, g_krel);
    cudaGetSymbolAddress((void**)&vrel, g_vrel);
    cudaGetSymbolAddress((void**)&logits, g_logits);
    cudaGetSymbolAddress((void**)&mx, g_mx);
    cudaGetSymbolAddress((void**)&den, g_den);
    cudaGetSymbolAddress((void**)&agg, g_agg);
    cudaGetSymbolAddress((void**)&htmp, g_htmp);
    cudaGetSymbolAddress((void**)&wf, g_wf);
    cudaGetSymbolAddress((void**)&bf, g_bf);

    // node-type offsets within the unified [NN] index space
    const int offT3[3] = { 0, Nh, Nh + Ni };               // herb, ing, tgt
    // rel slot offsets per edge type (src-type instance)
    const int slotOff[4] = { 0, Nh, Nh + Ni, Nh + 2 * Ni };
    // dst node-type offset per edge type
    const int dstOff[4] = { Nh, 0, Nh + Ni, Nh };          // ing, herb, tgt, ing
    // src type of each edge type (for xs base)
    const int srcOff[4] = { 0, Nh, Nh, Nh + Ni };

    // 1) init accumulators
    {
        int total = NN * HID + 2 * NN * NHEAD;
        init_buffers<<<cdiv(total, 256), 256>>>(agg, den, mx, NN * HID, NN * NHEAD);
    }

    // 2) fused relation weights
    fuse_rel_weights<<<8, 256>>>(Wk, bk, Wv, bv, a_rel, m_rel, wf, bf);

    // 3) input projections -> xs
    sgemm128<<<cdiv(Nh,TM),256>>>(x_herb, W_herb, b_herb, xs,                     Nh, 400, 0, nullptr, nullptr, 0);
    sgemm128<<<cdiv(Ni,TM),256>>>(x_ing,  W_ing,  b_ing,  xs + (size_t)Nh*HID,    Ni, 300, 0, nullptr, nullptr, 0);
    sgemm128<<<cdiv(Nt,TM),256>>>(x_tgt,  W_tgt,  b_tgt,  xs + (size_t)(Nh+Ni)*HID, Nt, 200, 0, nullptr, nullptr, 0);

    // 4) per-type q
    const int Ntype[3] = { Nh, Ni, Nt };
    for (int i = 0; i < 3; ++i) {
        sgemm128<<<cdiv(Ntype[i],TM),256>>>(xs + (size_t)offT3[i]*HID,
                                            Wq + (size_t)i*HID*HID, bq + i*HID,
                                            q + (size_t)offT3[i]*HID,
                                            Ntype[i], HID, 0, nullptr, nullptr, 0);
    }
    // 5) per-edge-type fused k_rel / v_rel
    const int srcN[4] = { Nh, Ni, Ni, Nt };
    for (int e = 0; e < 4; ++e) {
        sgemm128<<<cdiv(srcN[e],TM),256>>>(xs + (size_t)srcOff[e]*HID,
                                           wf + (size_t)(e*2+0)*HID*HID, bf + (e*2+0)*HID,
                                           krel + (size_t)slotOff[e]*HID,
                                           srcN[e], HID, 0, nullptr, nullptr, 0);
        sgemm128<<<cdiv(srcN[e],TM),256>>>(xs + (size_t)srcOff[e]*HID,
                                           wf + (size_t)(e*2+1)*HID*HID, bf + (e*2+1)*HID,
                                           vrel + (size_t)slotOff[e]*HID,
                                           srcN[e], HID, 0, nullptr, nullptr, 0);
    }

    // 6) edge pass A (logits + segment max)
    size_t loff = 0;
    size_t loffs[4];
    for (int e = 0; e < 4; ++e) { loffs[e] = loff; loff += (size_t)E[e] * NHEAD; }
    for (int e = 0; e < 4; ++e) {
        edge_pass_a<<<2048, 256>>>(src_e[e], dst_e[e], E[e],
                                   q + (size_t)dstOff[e]*HID,
                                   krel + (size_t)slotOff[e]*HID,
                                   logits + loffs[e],
                                   mx + (size_t)dstOff[e]*NHEAD,
                                   p_rel + e*NHEAD);
    }

    // 7) edge pass B (softmax denominator + weighted aggregation)
    for (int e = 0; e < 4; ++e) {
        edge_pass_b<<<2048, 256>>>(src_e[e], dst_e[e], E[e],
                                   logits + loffs[e],
                                   mx + (size_t)dstOff[e]*NHEAD,
                                   vrel + (size_t)slotOff[e]*HID,
                                   den + (size_t)dstOff[e]*NHEAD,
                                   agg + (size_t)dstOff[e]*HID);
    }

    // 8) normalize + gelu  (reuse q buffer)
    float* gbuf = q;
    norm_gelu<<<cdiv(NN*HID, 256), 256>>>(agg, den, gbuf, NN * HID);

    // 9) output linear + skip gate + relu per type
    float* outp = (float*)d_out;
    float* Cdst[3] = { htmp, outp + (size_t)Nh*HID, outp + (size_t)(Nh+Ni)*HID };
    for (int i = 0; i < 3; ++i) {
        sgemm128<<<cdiv(Ntype[i],TM),256>>>(gbuf + (size_t)offT3[i]*HID,
                                            Wa + (size_t)i*HID*HID, ba + i*HID,
                                            Cdst[i], Ntype[i], HID, 1,
                                            xs + (size_t)offT3[i]*HID, skip, i);
    }

    // 10) final herb linear
    sgemm128<<<cdiv(Nh,TM),256>>>(htmp, W_out, b_out, outp, Nh, HID, 0, nullptr, nullptr, 0);
}

// round 2
// speedup vs baseline: 1.0613x; 1.0613x over previous
#include <cuda_runtime.h>
#include <cstdint>
#include <math.h>

// ---------------------------------------------------------------------------
// Problem constants
// ---------------------------------------------------------------------------
#define HID 128
#define NHEAD 8
#define HDIM 16

#define NH_MAX 8000
#define NI_MAX 40000
#define NT_MAX 20000
#define NN_MAX (NH_MAX + NI_MAX + NT_MAX)           // 68000
#define NREL_MAX (NH_MAX + 2*NI_MAX + NT_MAX)       // 108000
#define MAXE 250000

// ---------------------------------------------------------------------------
// Device scratch
// ---------------------------------------------------------------------------
__device__ float g_xs   [(size_t)NN_MAX   * HID];
__device__ float g_q    [(size_t)NN_MAX   * HID];
__device__ float g_krel [(size_t)NREL_MAX * HID];
__device__ float g_vrel [(size_t)NREL_MAX * HID];
__device__ float g_logits[(size_t)4 * MAXE * NHEAD];
__device__ float g_mx   [(size_t)NN_MAX * NHEAD];
__device__ float g_den  [(size_t)NN_MAX * NHEAD];
__device__ float g_agg  [(size_t)NN_MAX * HID];
__device__ float g_htmp [(size_t)NH_MAX * HID];
__device__ float g_wf   [8 * HID * HID];
__device__ float g_bf   [8 * HID];

// ---------------------------------------------------------------------------
__global__ void init_buffers(float* __restrict__ agg, float* __restrict__ den,
                             float* __restrict__ mx, int nAgg, int nDH)
{
    int idx = blockIdx.x * blockDim.x + threadIdx.x;
    int total = nAgg + 2 * nDH;
    if (idx >= total) return;
    if (idx < nAgg)            agg[idx] = 0.0f;
    else if (idx < nAgg + nDH) den[idx - nAgg] = 0.0f;
    else                       mx[idx - nAgg - nDH] = -INFINITY;
}

// ---------------------------------------------------------------------------
// Fuse Wk/Wv with per-edge-type relation matrices (block-diagonal product).
// ---------------------------------------------------------------------------
__global__ void fuse_rel_weights(const float* __restrict__ Wk, const float* __restrict__ bk,
                                 const float* __restrict__ Wv, const float* __restrict__ bv,
                                 const float* __restrict__ a_rel, const float* __restrict__ m_rel,
                                 float* __restrict__ Wf, float* __restrict__ bf)
{
    int slot = blockIdx.x;
    int e = slot >> 1, kind = slot & 1;
    int s = (e == 0) ? 0 : ((e == 3) ? 2 : 1);
    const float* Wb = (kind ? Wv : Wk) + (size_t)s * HID * HID;
    const float* bb = (kind ? bv : bk) + (size_t)s * HID;
    const float* rel = (kind ? m_rel : a_rel) + (size_t)e * NHEAD * HDIM * HDIM;

    for (int idx = threadIdx.x; idx < HID * HID; idx += blockDim.x) {
        int i = idx >> 7, j = idx & 127;
        int h = j >> 4, j16 = j & 15;
        float acc = 0.0f;
        #pragma unroll
        for (int d = 0; d < HDIM; ++d)
            acc += Wb[i * HID + h * HDIM + d] * rel[(h * HDIM + d) * HDIM + j16];
        Wf[(size_t)slot * HID * HID + idx] = acc;
    }
    for (int j = threadIdx.x; j < HID; j += blockDim.x) {
        int h = j >> 4, j16 = j & 15;
        float acc = 0.0f;
        #pragma unroll
        for (int d = 0; d < HDIM; ++d)
            acc += bb[h * HDIM + d] * rel[(h * HDIM + d) * HDIM + j16];
        bf[slot * HID + j] = acc;
    }
}

// ---------------------------------------------------------------------------
// f32x2-packed SGEMM: C[M,128] = A[M,K] @ W[K,128] + bias, per column-block.
// Tile 128x128x16, 256 threads, 8x8 per-thread block as 32 f32x2 accumulators.
// blockIdx.y selects {W, bias, dst} (multi-headed projection fusion).
// mode 1: relu(g*C + (1-g)*xs), g = sigmoid(skipv[skipidx]).
// Requires K % 4 == 0.
// ---------------------------------------------------------------------------
#define GTM 128
#define GTK 16
#define GTMP (GTM + 4)

struct Blk  { const float* W; const float* bias; float* dst; };
struct Blk5 { Blk b[5]; };

typedef unsigned long long ull;

__global__ __launch_bounds__(256, 2)
void sgemm_f2(const float* __restrict__ A, int M, int K, Blk5 blks,
              int mode, const float* __restrict__ xs,
              const float* __restrict__ skipv, int skipidx)
{
    __shared__ float As[2][GTK][GTMP];   // transposed: [k][m], padded
    __shared__ float Bs[2][GTK][HID];    // [k][n]

    const int tid = threadIdx.x;
    const int m0 = blockIdx.x * GTM;
    const float* __restrict__ W    = blks.b[blockIdx.y].W;
    const float* __restrict__ bias = blks.b[blockIdx.y].bias;
    float* __restrict__ dst        = blks.b[blockIdx.y].dst;

    const int tr = tid >> 4;     // 0..15 -> rows tr*8..+7
    const int tc = tid & 15;     // 0..15 -> cols tc*8..+7

    ull acc2[8][4];
    #pragma unroll
    for (int i = 0; i < 8; ++i)
        #pragma unroll
        for (int j = 0; j < 4; ++j) acc2[i][j] = 0ull;

    // loader lanes
    const int ar = tid >> 2;            // 0..63 (+64)
    const int ak = (tid & 3) << 2;      // 0,4,8,12
    const int bk = tid >> 5;            // 0..7 (+8)
    const int bc = (tid & 31) << 2;     // 0..124

    const int ktiles = (K + GTK - 1) / GTK;

    // prologue: tile 0 -> buf 0
    {
        #pragma unroll
        for (int h = 0; h < 2; ++h) {
            int gr = m0 + ar + h * 64;
            float4 v = make_float4(0.f, 0.f, 0.f, 0.f);
            if (gr < M && ak + 3 < K)
                v = *reinterpret_cast<const float4*>(A + (size_t)gr * K + ak);
            As[0][ak + 0][ar + h * 64] = v.x;
            As[0][ak + 1][ar + h * 64] = v.y;
            As[0][ak + 2][ar + h * 64] = v.z;
            As[0][ak + 3][ar + h * 64] = v.w;
        }
        #pragma unroll
        for (int h = 0; h < 2; ++h) {
            int gk = bk + h * 8;
            float4 v = make_float4(0.f, 0.f, 0.f, 0.f);
            if (gk < K)
                v = *reinterpret_cast<const float4*>(W + (size_t)gk * HID + bc);
            *reinterpret_cast<float4*>(&Bs[0][bk + h * 8][bc]) = v;
        }
    }
    __syncthreads();

    for (int kt = 0; kt < ktiles; ++kt) {
        const int cur = kt & 1;
        const int nxt = cur ^ 1;
        const bool has = (kt + 1 < ktiles);
        float4 pa[2], pb[2];
        if (has) {
            const int k0 = (kt + 1) * GTK;
            #pragma unroll
            for (int h = 0; h < 2; ++h) {
                int gr = m0 + ar + h * 64, gk = k0 + ak;
                pa[h] = make_float4(0.f, 0.f, 0.f, 0.f);
                if (gr < M && gk + 3 < K)
                    pa[h] = *reinterpret_cast<const float4*>(A + (size_t)gr * K + gk);
            }
            #pragma unroll
            for (int h = 0; h < 2; ++h) {
                int gk = k0 + bk + h * 8;
                pb[h] = make_float4(0.f, 0.f, 0.f, 0.f);
                if (gk < K)
                    pb[h] = *reinterpret_cast<const float4*>(W + (size_t)gk * HID + bc);
            }
        }

        #pragma unroll
        for (int kk = 0; kk < GTK; ++kk) {
            float4 a0 = *reinterpret_cast<const float4*>(&As[cur][kk][tr * 8]);
            float4 a1 = *reinterpret_cast<const float4*>(&As[cur][kk][tr * 8 + 4]);
            float4 b0 = *reinterpret_cast<const float4*>(&Bs[cur][kk][tc * 8]);
            float4 b1 = *reinterpret_cast<const float4*>(&Bs[cur][kk][tc * 8 + 4]);
            ull b2[4], a2[8];
            asm("mov.b64 %0, {%1, %2};" : "=l"(b2[0]) : "f"(b0.x), "f"(b0.y));
            asm("mov.b64 %0, {%1, %2};" : "=l"(b2[1]) : "f"(b0.z), "f"(b0.w));
            asm("mov.b64 %0, {%1, %2};" : "=l"(b2[2]) : "f"(b1.x), "f"(b1.y));
            asm("mov.b64 %0, {%1, %2};" : "=l"(b2[3]) : "f"(b1.z), "f"(b1.w));
            float av[8] = {a0.x, a0.y, a0.z, a0.w, a1.x, a1.y, a1.z, a1.w};
            #pragma unroll
            for (int i = 0; i < 8; ++i)
                asm("mov.b64 %0, {%1, %1};" : "=l"(a2[i]) : "f"(av[i]));
            #pragma unroll
            for (int i = 0; i < 8; ++i)
                #pragma unroll
                for (int j = 0; j < 4; ++j)
                    asm("fma.rn.f32x2 %0, %1, %2, %0;"
                        : "+l"(acc2[i][j]) : "l"(a2[i]), "l"(b2[j]));
        }

        if (has) {
            #pragma unroll
            for (int h = 0; h < 2; ++h) {
                As[nxt][ak + 0][ar + h * 64] = pa[h].x;
                As[nxt][ak + 1][ar + h * 64] = pa[h].y;
                As[nxt][ak + 2][ar + h * 64] = pa[h].z;
                As[nxt][ak + 3][ar + h * 64] = pa[h].w;
            }
            #pragma unroll
            for (int h = 0; h < 2; ++h)
                *reinterpret_cast<float4*>(&Bs[nxt][bk + h * 8][bc]) = pb[h];
            __syncthreads();
        }
    }

    // epilogue
    float4 bv0 = *reinterpret_cast<const float4*>(bias + tc * 8);
    float4 bv1 = *reinterpret_cast<const float4*>(bias + tc * 8 + 4);
    float bb[8] = {bv0.x, bv0.y, bv0.z, bv0.w, bv1.x, bv1.y, bv1.z, bv1.w};
    float g = 0.0f, hg = 0.0f;
    if (mode == 1) {
        g = 1.0f / (1.0f + expf(-skipv[skipidx]));
        hg = 1.0f - g;
    }

    #pragma unroll
    for (int i = 0; i < 8; ++i) {
        int gr = m0 + tr * 8 + i;
        if (gr >= M) continue;
        float o[8];
        #pragma unroll
        for (int j = 0; j < 4; ++j)
            asm("mov.b64 {%0, %1}, %2;" : "=f"(o[2 * j]), "=f"(o[2 * j + 1]) : "l"(acc2[i][j]));
        #pragma unroll
        for (int j = 0; j < 8; ++j) o[j] += bb[j];
        if (mode == 1) {
            float4 x0 = *reinterpret_cast<const float4*>(xs + (size_t)gr * HID + tc * 8);
            float4 x1 = *reinterpret_cast<const float4*>(xs + (size_t)gr * HID + tc * 8 + 4);
            float xv[8] = {x0.x, x0.y, x0.z, x0.w, x1.x, x1.y, x1.z, x1.w};
            #pragma unroll
            for (int j = 0; j < 8; ++j)
                o[j] = fmaxf(0.0f, g * o[j] + hg * xv[j]);
        }
        float4 o0 = make_float4(o[0], o[1], o[2], o[3]);
        float4 o1 = make_float4(o[4], o[5], o[6], o[7]);
        *reinterpret_cast<float4*>(dst + (size_t)gr * HID + tc * 8)     = o0;
        *reinterpret_cast<float4*>(dst + (size_t)gr * HID + tc * 8 + 4) = o1;
    }
}

// ---------------------------------------------------------------------------
// Edge pass A: logits + segment max (1 warp / edge)
// ---------------------------------------------------------------------------
__global__ __launch_bounds__(256)
void edge_pass_a(const int* __restrict__ src, const int* __restrict__ dst, int E,
                 const float* __restrict__ q, const float* __restrict__ krel,
                 float* __restrict__ logits, float* __restrict__ mx,
                 const float* __restrict__ prel)
{
    const int lane = threadIdx.x & 31;
    const int head = lane >> 2;
    const float scale = __ldg(prel + head) * 0.25f;
    int warp = (blockIdx.x * blockDim.x + threadIdx.x) >> 5;
    const int nwarp = (gridDim.x * blockDim.x) >> 5;

    for (int e = warp; e < E; e += nwarp) {
        int s = __ldg(src + e);
        int d = __ldg(dst + e);
        float4 qv = *reinterpret_cast<const float4*>(q    + (size_t)d * HID + lane * 4);
        float4 kv = *reinterpret_cast<const float4*>(krel + (size_t)s * HID + lane * 4);
        float p = qv.x * kv.x + qv.y * kv.y + qv.z * kv.z + qv.w * kv.w;
        p += __shfl_xor_sync(0xffffffffu, p, 1);
        p += __shfl_xor_sync(0xffffffffu, p, 2);
        float lg = p * scale;
        if ((lane & 3) == 0) {
            logits[(size_t)e * NHEAD + head] = lg;
            float* a = mx + (size_t)d * NHEAD + head;
            if (lg >= 0.0f) atomicMax((int*)a, __float_as_int(lg));
            else            atomicMin((unsigned int*)a, __float_as_uint(lg));
        }
    }
}

// ---------------------------------------------------------------------------
// Edge pass B: softmax denominator + weighted aggregation (red.global.v4)
// ---------------------------------------------------------------------------
__global__ __launch_bounds__(256)
void edge_pass_b(const int* __restrict__ src, const int* __restrict__ dst, int E,
                 const float* __restrict__ logits, const float* __restrict__ mx,
                 const float* __restrict__ vrel,
                 float* __restrict__ den, float* __restrict__ agg)
{
    const int lane = threadIdx.x & 31;
    const int head = lane >> 2;
    int warp = (blockIdx.x * blockDim.x + threadIdx.x) >> 5;
    const int nwarp = (gridDim.x * blockDim.x) >> 5;

    for (int e = warp; e < E; e += nwarp) {
        int s = __ldg(src + e);
        int d = __ldg(dst + e);
        float lg = __ldg(logits + (size_t)e * NHEAD + head);
        float m  = __ldg(mx + (size_t)d * NHEAD + head);
        float ex = __expf(lg - m);
        if ((lane & 3) == 0)
            atomicAdd(den + (size_t)d * NHEAD + head, ex);
        float4 vv = *reinterpret_cast<const float4*>(vrel + (size_t)s * HID + lane * 4);
        float* a = agg + (size_t)d * HID + lane * 4;
        asm volatile("red.global.add.v4.f32 [%0], {%1,%2,%3,%4};"
                     :: "l"(a), "f"(ex * vv.x), "f"(ex * vv.y),
                        "f"(ex * vv.z), "f"(ex * vv.w)
                     : "memory");
    }
}

// ---------------------------------------------------------------------------
__global__ void norm_gelu(const float* __restrict__ agg, const float* __restrict__ den,
                          float* __restrict__ out, int total)
{
    int idx = blockIdx.x * blockDim.x + threadIdx.x;
    if (idx >= total) return;
    int n = idx >> 7;
    int h = (idx >> 4) & 7;
    float x = agg[idx] / (den[n * NHEAD + h] + 1e-16f);
    out[idx] = 0.5f * x * (1.0f + erff(x * 0.70710678118654752f));
}

// ---------------------------------------------------------------------------
static inline int cdiv(int a, int b) { return (a + b - 1) / b; }

extern "C" void kernel_launch(void* const* d_in, const int* in_sizes, int n_in,
                              void* d_out, int out_size)
{
    const float* x_herb = (const float*)d_in[0];
    const float* x_ing  = (const float*)d_in[1];
    const float* x_tgt  = (const float*)d_in[2];
    const float* W_herb = (const float*)d_in[3];
    const float* b_herb = (const float*)d_in[4];
    const float* W_ing  = (const float*)d_in[5];
    const float* b_ing  = (const float*)d_in[6];
    const float* W_tgt  = (const float*)d_in[7];
    const float* b_tgt  = (const float*)d_in[8];
    const float* Wk     = (const float*)d_in[9];
    const float* bk     = (const float*)d_in[10];
    const float* Wq     = (const float*)d_in[11];
    const float* bq     = (const float*)d_in[12];
    const float* Wv     = (const float*)d_in[13];
    const float* bv     = (const float*)d_in[14];
    const float* a_rel  = (const float*)d_in[15];
    const float* m_rel  = (const float*)d_in[16];
    const float* p_rel  = (const float*)d_in[17];
    const float* Wa     = (const float*)d_in[18];
    const float* ba     = (const float*)d_in[19];
    const float* skip   = (const float*)d_in[20];
    const float* W_out  = (const float*)d_in[21];
    const float* b_out  = (const float*)d_in[22];
    const int* src_e[4] = { (const int*)d_in[23], (const int*)d_in[25],
                            (const int*)d_in[27], (const int*)d_in[29] };
    const int* dst_e[4] = { (const int*)d_in[24], (const int*)d_in[26],
                            (const int*)d_in[28], (const int*)d_in[30] };

    const int Nh = in_sizes[0] / 400;
    const int Ni = in_sizes[1] / 300;
    const int Nt = in_sizes[2] / 200;
    const int NN = Nh + Ni + Nt;
    int E[4] = { in_sizes[23], in_sizes[25], in_sizes[27], in_sizes[29] };

    float *xs, *q, *krel, *vrel, *logits, *mx, *den, *agg, *htmp, *wf, *bf;
    cudaGetSymbolAddress((void**)&xs, g_xs);
    cudaGetSymbolAddress((void**)&q, g_q);
    cudaGetSymbolAddress((void**)&krel, g_krel);
    cudaGetSymbolAddress((void**)&vrel, g_vrel);
    cudaGetSymbolAddress((void**)&logits, g_logits);
    cudaGetSymbolAddress((void**)&mx, g_mx);
    cudaGetSymbolAddress((void**)&den, g_den);
    cudaGetSymbolAddress((void**)&agg, g_agg);
    cudaGetSymbolAddress((void**)&htmp, g_htmp);
    cudaGetSymbolAddress((void**)&wf, g_wf);
    cudaGetSymbolAddress((void**)&bf, g_bf);

    const int offT3[3]   = { 0, Nh, Nh + Ni };
    const int slotOff[4] = { 0, Nh, Nh + Ni, Nh + 2 * Ni };
    const int dstOff[4]  = { Nh, 0, Nh + Ni, Nh };
    const int Ntype[3]   = { Nh, Ni, Nt };

    // 1) init accumulators
    {
        int total = NN * HID + 2 * NN * NHEAD;
        init_buffers<<<cdiv(total, 256), 256>>>(agg, den, mx, NN * HID, NN * NHEAD);
    }

    // 2) fused relation weights
    fuse_rel_weights<<<8, 256>>>(Wk, bk, Wv, bv, a_rel, m_rel, wf, bf);

    // 3) input projections -> xs
    {
        Blk5 B{}; B.b[0] = { W_herb, b_herb, xs };
        sgemm_f2<<<dim3(cdiv(Nh,GTM),1),256>>>(x_herb, Nh, 400, B, 0, nullptr, nullptr, 0);
    }
    {
        Blk5 B{}; B.b[0] = { W_ing, b_ing, xs + (size_t)Nh*HID };
        sgemm_f2<<<dim3(cdiv(Ni,GTM),1),256>>>(x_ing, Ni, 300, B, 0, nullptr, nullptr, 0);
    }
    {
        Blk5 B{}; B.b[0] = { W_tgt, b_tgt, xs + (size_t)(Nh+Ni)*HID };
        sgemm_f2<<<dim3(cdiv(Nt,GTM),1),256>>>(x_tgt, Nt, 200, B, 0, nullptr, nullptr, 0);
    }

    // 4) fused q / k_rel / v_rel per source node type
    {   // herb: q0 + edge type 0 (k,v)
        Blk5 B{};
        B.b[0] = { Wq,                 bq,           q };
        B.b[1] = { wf + 0*HID*HID,     bf + 0*HID,   krel + (size_t)slotOff[0]*HID };
        B.b[2] = { wf + 1*HID*HID,     bf + 1*HID,   vrel + (size_t)slotOff[0]*HID };
        sgemm_f2<<<dim3(cdiv(Nh,GTM),3),256>>>(xs, Nh, HID, B, 0, nullptr, nullptr, 0);
    }
    {   // ing: q1 + edge types 1,2 (k,v each)
        Blk5 B{};
        B.b[0] = { Wq + (size_t)1*HID*HID, bq + 1*HID, q + (size_t)Nh*HID };
        B.b[1] = { wf + 2*HID*HID, bf + 2*HID, krel + (size_t)slotOff[1]*HID };
        B.b[2] = { wf + 3*HID*HID, bf + 3*HID, vrel + (size_t)slotOff[1]*HID };
        B.b[3] = { wf + 4*HID*HID, bf + 4*HID, krel + (size_t)slotOff[2]*HID };
        B.b[4] = { wf + 5*HID*HID, bf + 5*HID, vrel + (size_t)slotOff[2]*HID };
        sgemm_f2<<<dim3(cdiv(Ni,GTM),5),256>>>(xs + (size_t)Nh*HID, Ni, HID, B, 0, nullptr, nullptr, 0);
    }
    {   // tgt: q2 + edge type 3 (k,v)
        Blk5 B{};
        B.b[0] = { Wq + (size_t)2*HID*HID, bq + 2*HID, q + (size_t)(Nh+Ni)*HID };
        B.b[1] = { wf + 6*HID*HID, bf + 6*HID, krel + (size_t)slotOff[3]*HID };
        B.b[2] = { wf + 7*HID*HID, bf + 7*HID, vrel + (size_t)slotOff[3]*HID };
        sgemm_f2<<<dim3(cdiv(Nt,GTM),3),256>>>(xs + (size_t)(Nh+Ni)*HID, Nt, HID, B, 0, nullptr, nullptr, 0);
    }

    // 5) edge pass A
    size_t loff = 0, loffs[4];
    for (int e = 0; e < 4; ++e) { loffs[e] = loff; loff += (size_t)E[e] * NHEAD; }
    for (int e = 0; e < 4; ++e) {
        edge_pass_a<<<2048, 256>>>(src_e[e], dst_e[e], E[e],
                                   q + (size_t)dstOff[e]*HID,
                                   krel + (size_t)slotOff[e]*HID,
                                   logits + loffs[e],
                                   mx + (size_t)dstOff[e]*NHEAD,
                                   p_rel + e*NHEAD);
    }

    // 6) edge pass B
    for (int e = 0; e < 4; ++e) {
        edge_pass_b<<<2048, 256>>>(src_e[e], dst_e[e], E[e],
                                   logits + loffs[e],
                                   mx + (size_t)dstOff[e]*NHEAD,
                                   vrel + (size_t)slotOff[e]*HID,
                                   den + (size_t)dstOff[e]*NHEAD,
                                   agg + (size_t)dstOff[e]*HID);
    }

    // 7) normalize + gelu (reuse q buffer)
    float* gbuf = q;
    norm_gelu<<<cdiv(NN*HID, 256), 256>>>(agg, den, gbuf, NN * HID);

    // 8) output linear + skip gate + relu per type
    float* outp = (float*)d_out;
    float* Cdst[3] = { htmp, outp + (size_t)Nh*HID, outp + (size_t)(Nh+Ni)*HID };
    for (int i = 0; i < 3; ++i) {
        Blk5 B{};
        B.b[0] = { Wa + (size_t)i*HID*HID, ba + i*HID, Cdst[i] };
        sgemm_f2<<<dim3(cdiv(Ntype[i],GTM),1),256>>>(gbuf + (size_t)offT3[i]*HID,
                                                     Ntype[i], HID, B, 1,
                                                     xs + (size_t)offT3[i]*HID, skip, i);
    }

    // 9) final herb linear
    {
        Blk5 B{}; B.b[0] = { W_out, b_out, outp };
        sgemm_f2<<<dim3(cdiv(Nh,GTM),1),256>>>(htmp, Nh, HID, B, 0, nullptr, nullptr, 0);
    }
}